// round 9
// baseline (speedup 1.0000x reference)
#include <cuda_runtime.h>
#include <cuda_fp16.h>
#include <cuda_bf16.h>
#include <math.h>
#include <type_traits>

// ---------------------------------------------------------------------------
// GATLayers round 9 = R8 + gemm2 on tensor cores via split-fp16 (hi+lo):
//   A@B ~= Ahi@Bhi + Alo@Bhi + Ahi@Blo   (residual ~2^-22, near-fp32 exact)
// agg2 emits y2 as hi/lo fp16; prep builds W2^T hi/lo. All else = R8.
// ---------------------------------------------------------------------------

constexpr int NN = 20000;
constexpr int EE = 640000;
constexpr int CB = (NN + 255) / 256;   // 79 scan blocks
constexpr int GB = (NN + 63) / 64;     // 313 gemm1 row-blocks
constexpr int GB2 = (NN + 127) / 128;  // 157 gemm2 row-blocks

// ------------------------------ scratch ------------------------------------
__device__ int    g_is64;
__device__ int    g_ready;
__device__ int    g_done;
__device__ int    g_tick;
__device__ int    g_deg[NN];
__device__ int    g_rowptr[NN + 1];
__device__ int    g_rank[EE];
__device__ int    g_col[EE];
__device__ int    g_bsum[CB];
__device__ __half g_x16[NN * 64];
__device__ __half g_h16[NN * 128];
__device__ __half g_w2hi[256 * 128];   // W2^T hi fp16: [n][k]
__device__ __half g_w2lo[256 * 128];   // W2^T lo fp16
__device__ __half g_y2hi[NN * 256];    // aggregated layer2 hi
__device__ __half g_y2lo[NN * 256];    // aggregated layer2 lo
__device__ float  g_y1[NN * 128];
__device__ float  g_out1[NN * 128];
__device__ float  g_out2[NN * 256];
__device__ float  g_as1[NN * 2];
__device__ float  g_ad1[NN * 2];
__device__ float  g_as2[NN * 2];
__device__ float  g_ad2[NN * 2];
__device__ float  g_part[GB * 2 * 256];
__device__ float  g_scale[256];
__device__ float  g_shift[256];
__device__ float4 g_u1[64];
__device__ float4 g_u2[128];

// --------------------------- f32x2 helpers ----------------------------------
__device__ __forceinline__ unsigned long long pack2(float lo, float hi) {
    unsigned long long r;
    asm("mov.b64 %0, {%1, %2};" : "=l"(r)
        : "r"(__float_as_uint(lo)), "r"(__float_as_uint(hi)));
    return r;
}
__device__ __forceinline__ void unpk2(unsigned long long v, float& x, float& y) {
    unsigned a, b;
    asm("mov.b64 {%0, %1}, %2;" : "=r"(a), "=r"(b) : "l"(v));
    x = __uint_as_float(a); y = __uint_as_float(b);
}
__device__ __forceinline__ void ffma2(unsigned long long& d,
                                      unsigned long long a,
                                      unsigned long long b) {
    asm("fma.rn.f32x2 %0, %1, %2, %0;" : "+l"(d) : "l"(a), "l"(b));
}
__device__ __forceinline__ void split16(float v, __half& h, __half& l) {
    h = __float2half_rn(v);
    l = __float2half_rn(v - __half2float(h));   // Sterbenz: exact residual
}

// ----------------- prep: deg zero + detect + attvec + W2 split --------------
__global__ __launch_bounds__(256) void prep_kernel(
    const int* __restrict__ ei32,
    const float* __restrict__ W1, const float* __restrict__ s1,
    const float* __restrict__ d1,
    const float* __restrict__ W2, const float* __restrict__ s2,
    const float* __restrict__ d2)
{
    const int bx = blockIdx.x;
    if (bx < 79) {
        int i = bx * 256 + threadIdx.x;
        if (i < NN) g_deg[i] = 0;
        if (bx == 0 && threadIdx.x < 32) {
            int lane = threadIdx.x;
            int a = ei32[2 * lane + 1];
            int b = ei32[2 * (lane + 32) + 1];
            unsigned m = __ballot_sync(0xffffffffu, (a | b) != 0);
            if (lane == 0) g_is64 = (m == 0) ? 1 : 0;
        }
        return;
    }
    if (bx < 103) {
        const int lane = threadIdx.x & 31;
        const int f = (bx - 79) * 8 + (threadIdx.x >> 5);   // 0..191
        float4 u = make_float4(0.f, 0.f, 0.f, 0.f);
        if (f < 64) {
            #pragma unroll
            for (int c = lane; c < 64; c += 32) {
                float w0 = W1[f * 128 + c], w1 = W1[f * 128 + 64 + c];
                u.x += w0 * s1[c];      u.y += w1 * s1[64 + c];
                u.z += w0 * d1[c];      u.w += w1 * d1[64 + c];
            }
        } else {
            int f2 = f - 64;
            #pragma unroll
            for (int c = lane; c < 128; c += 32) {
                float w0 = W2[f2 * 256 + c], w1 = W2[f2 * 256 + 128 + c];
                u.x += w0 * s2[c];      u.y += w1 * s2[128 + c];
                u.z += w0 * d2[c];      u.w += w1 * d2[128 + c];
            }
        }
        #pragma unroll
        for (int o = 16; o; o >>= 1) {
            u.x += __shfl_xor_sync(0xffffffffu, u.x, o);
            u.y += __shfl_xor_sync(0xffffffffu, u.y, o);
            u.z += __shfl_xor_sync(0xffffffffu, u.z, o);
            u.w += __shfl_xor_sync(0xffffffffu, u.w, o);
        }
        if (lane == 0) {
            if (f < 64) g_u1[f] = u;
            else        g_u2[f - 64] = u;
        }
        return;
    }
    // W2^T split-fp16: blocks 103..134, 32768 elements
    int t4 = (bx - 103) * 256 + threadIdx.x;       // 0..8191
    int e = t4 * 4;
    int k = e >> 8;                                 // 0..127
    int n0 = e & 255;
    float4 w = *(const float4*)&W2[k * 256 + n0];
    __half h, l;
    split16(w.x, h, l); g_w2hi[(n0 + 0) * 128 + k] = h; g_w2lo[(n0 + 0) * 128 + k] = l;
    split16(w.y, h, l); g_w2hi[(n0 + 1) * 128 + k] = h; g_w2lo[(n0 + 1) * 128 + k] = l;
    split16(w.z, h, l); g_w2hi[(n0 + 2) * 128 + k] = h; g_w2lo[(n0 + 2) * 128 + k] = l;
    split16(w.w, h, l); g_w2hi[(n0 + 3) * 128 + k] = h; g_w2lo[(n0 + 3) * 128 + k] = l;
}

// -------------------------- CSR construction -------------------------------
__device__ __forceinline__ int edge_val(const void* ei, int idx, int is64) {
    if (is64) return (int)((const long long*)ei)[idx];
    return ((const int*)ei)[idx];
}

__global__ void hist_kernel(const void* __restrict__ ei) {
    int e = blockIdx.x * blockDim.x + threadIdx.x;
    if (e >= EE) return;
    int dst = edge_val(ei, EE + e, g_is64);
    g_rank[e] = atomicAdd(&g_deg[dst], 1);
}

__global__ __launch_bounds__(256) void rowptr_kernel() {
    __shared__ int s[256];
    const int t = threadIdx.x;
    const int bx = blockIdx.x;
    const int i = bx * 256 + t;
    int d = (i < NN) ? g_deg[i] : 0;
    s[t] = d;
    __syncthreads();
    for (int o = 1; o < 256; o <<= 1) {
        int u = (t >= o) ? s[t - o] : 0;
        __syncthreads();
        s[t] += u;
        __syncthreads();
    }
    const int incl = s[t];
    if (t == 255) {
        g_bsum[bx] = incl;
        __threadfence();
        atomicAdd(&g_ready, 1);
        while (atomicAdd(&g_ready, 0) < (int)gridDim.x) {}
    }
    __syncthreads();
    int pre = 0;
    for (int b = t; b < bx; b += 256) pre += g_bsum[b];
    #pragma unroll
    for (int o = 16; o; o >>= 1) pre += __shfl_xor_sync(0xffffffffu, pre, o);
    __shared__ int ws[8];
    if ((t & 31) == 0) ws[t >> 5] = pre;
    __syncthreads();
    if (t == 0) {
        int p = 0;
        #pragma unroll
        for (int w = 0; w < 8; w++) p += ws[w];
        s[0] = p;
    }
    __syncthreads();
    const int bpre = s[0];
    if (i < NN) g_rowptr[i] = bpre + incl - d;
    if (i == NN - 1) g_rowptr[NN] = bpre + incl;
    if (t == 0 && atomicAdd(&g_done, 1) == (int)gridDim.x - 1) {
        g_ready = 0;
        g_done = 0;
    }
}

// ---------------- fused scatter (blocks < SB) + gemv1 (rest) ----------------
constexpr int SB = EE / 256;

template <int K, bool BN>
__device__ __forceinline__ void gemv_body(
    int node, const float* __restrict__ A, const float4* __restrict__ U,
    float* __restrict__ as_out, float* __restrict__ ad_out,
    __half* __restrict__ h16, int lane)
{
    float4 acc = make_float4(0.f, 0.f, 0.f, 0.f);
    #pragma unroll
    for (int f = lane; f < K; f += 32) {
        float v = A[(size_t)node * K + f];
        if (BN) { v = v * g_scale[f] + g_shift[f]; v = v > 0.f ? v : 0.f; }
        h16[(size_t)node * K + f] = __float2half_rn(v);
        float4 u = U[f];
        acc.x += v * u.x; acc.y += v * u.y;
        acc.z += v * u.z; acc.w += v * u.w;
    }
    #pragma unroll
    for (int o = 16; o; o >>= 1) {
        acc.x += __shfl_xor_sync(0xffffffffu, acc.x, o);
        acc.y += __shfl_xor_sync(0xffffffffu, acc.y, o);
        acc.z += __shfl_xor_sync(0xffffffffu, acc.z, o);
        acc.w += __shfl_xor_sync(0xffffffffu, acc.w, o);
    }
    if (lane == 0) {
        as_out[node * 2 + 0] = acc.x;
        as_out[node * 2 + 1] = acc.y;
        ad_out[node * 2 + 0] = acc.z;
        ad_out[node * 2 + 1] = acc.w;
    }
}

__global__ __launch_bounds__(256) void scatter_gemv1_kernel(
    const void* __restrict__ ei, const float* __restrict__ x,
    const float4* __restrict__ U,
    float* __restrict__ as_out, float* __restrict__ ad_out,
    __half* __restrict__ x16)
{
    const int bx = blockIdx.x;
    if (bx < SB) {
        int e = bx * 256 + threadIdx.x;
        int is64 = g_is64;
        int src = edge_val(ei, e, is64);
        int dst = edge_val(ei, EE + e, is64);
        g_col[g_rowptr[dst] + g_rank[e]] = src;
        return;
    }
    const int node = (bx - SB) * 8 + (threadIdx.x >> 5);
    gemv_body<64, false>(node, x, U, as_out, ad_out, x16, threadIdx.x & 31);
}

__global__ __launch_bounds__(256) void gemv2_kernel(
    const float* __restrict__ A, const float4* __restrict__ U,
    float* __restrict__ as_out, float* __restrict__ ad_out,
    __half* __restrict__ h16)
{
    const int node = blockIdx.x * 8 + (threadIdx.x >> 5);
    gemv_body<128, true>(node, A, U, as_out, ad_out, h16, threadIdx.x & 31);
}

// ------------------- segment softmax + weighted aggregate ------------------
// Batched-32 edges per warp (each lane scores one edge; shfl broadcast).
// SPLIT: emit hi/lo fp16 y (layer 2); else fp32 (layer 1).
template <int F, bool SPLIT>
__global__ __launch_bounds__(256) void agg_kernel(
    const __half* __restrict__ src16, const float* __restrict__ as,
    const float* __restrict__ ad, float* __restrict__ y,
    __half* __restrict__ yhi, __half* __restrict__ ylo)
{
    const int lane = threadIdx.x & 31;
    const int warp = threadIdx.x >> 5;
    const int node = blockIdx.x * 8 + warp;
    constexpr int V = F / 32;
    using RowT = typename std::conditional<V == 2, unsigned, uint2>::type;
    const int base = g_rowptr[node];
    const int deg = g_rowptr[node + 1] - base;
    const float2* as2 = (const float2*)as;
    const float2 adi = ((const float2*)ad)[node];

    float acc0[V], acc1[V];
    #pragma unroll
    for (int v = 0; v < V; v++) { acc0[v] = 0.f; acc1[v] = 0.f; }
    float zp0 = 0.f, zp1 = 0.f;

    auto accum = [&](RowT u, float p0, float p1) {
        if constexpr (V == 2) {
            float2 f = __half22float2(*(__half2*)&u);
            acc0[0] += p0 * f.x; acc0[1] += p0 * f.y;
            acc1[0] += p1 * f.x; acc1[1] += p1 * f.y;
        } else {
            float2 f0 = __half22float2(*(__half2*)&u.x);
            float2 f1 = __half22float2(*(__half2*)&u.y);
            acc0[0] += p0 * f0.x; acc0[1] += p0 * f0.y;
            acc0[2] += p0 * f1.x; acc0[3] += p0 * f1.y;
            acc1[0] += p1 * f0.x; acc1[1] += p1 * f0.y;
            acc1[2] += p1 * f1.x; acc1[3] += p1 * f1.y;
        }
    };

    {   // self loop
        float2 a = as2[node];
        float e0 = a.x + adi.x; e0 = e0 > 0.f ? e0 : 0.2f * e0;
        float e1 = a.y + adi.y; e1 = e1 > 0.f ? e1 : 0.2f * e1;
        float p0 = __expf(e0), p1 = __expf(e1);
        if (lane == 0) { zp0 += p0; zp1 += p1; }
        RowT u = *(const RowT*)(src16 + (size_t)node * F + lane * V);
        accum(u, p0, p1);
    }

    for (int j0 = 0; j0 < deg; j0 += 32) {
        const int nb = min(32, deg - j0);
        int sl = 0; float p0 = 0.f, p1 = 0.f;
        if (lane < nb) {
            sl = g_col[base + j0 + lane];
            float2 a = as2[sl];
            float e0 = a.x + adi.x; e0 = e0 > 0.f ? e0 : 0.2f * e0;
            float e1 = a.y + adi.y; e1 = e1 > 0.f ? e1 : 0.2f * e1;
            p0 = __expf(e0); p1 = __expf(e1);
        }
        zp0 += p0; zp1 += p1;
        if (nb == 32) {
            #pragma unroll 8
            for (int k = 0; k < 32; k++) {
                int sk = __shfl_sync(0xffffffffu, sl, k);
                float q0 = __shfl_sync(0xffffffffu, p0, k);
                float q1 = __shfl_sync(0xffffffffu, p1, k);
                RowT u = *(const RowT*)(src16 + (size_t)sk * F + lane * V);
                accum(u, q0, q1);
            }
        } else {
            for (int k = 0; k < nb; k++) {
                int sk = __shfl_sync(0xffffffffu, sl, k);
                float q0 = __shfl_sync(0xffffffffu, p0, k);
                float q1 = __shfl_sync(0xffffffffu, p1, k);
                RowT u = *(const RowT*)(src16 + (size_t)sk * F + lane * V);
                accum(u, q0, q1);
            }
        }
    }

    #pragma unroll
    for (int o = 16; o; o >>= 1) {
        zp0 += __shfl_xor_sync(0xffffffffu, zp0, o);
        zp1 += __shfl_xor_sync(0xffffffffu, zp1, o);
    }
    const float i0 = 1.f / zp0, i1 = 1.f / zp1;

    if constexpr (SPLIT) {
        // V == 4: write hi/lo fp16 (split-fp16, near-exact)
        float v0[4], v1[4];
        #pragma unroll
        for (int v = 0; v < 4; v++) { v0[v] = acc0[v] * i0; v1[v] = acc1[v] * i1; }
        __half h[8], l[8];
        #pragma unroll
        for (int v = 0; v < 4; v++) split16(v0[v], h[v], l[v]);
        #pragma unroll
        for (int v = 0; v < 4; v++) split16(v1[v], h[4 + v], l[4 + v]);
        size_t off0 = (size_t)node * 2 * F + lane * 4;
        size_t off1 = off0 + F;
        *(uint2*)(yhi + off0) = *(uint2*)&h[0];
        *(uint2*)(yhi + off1) = *(uint2*)&h[4];
        *(uint2*)(ylo + off0) = *(uint2*)&l[0];
        *(uint2*)(ylo + off1) = *(uint2*)&l[4];
    } else {
        float* yr = y + (size_t)node * 2 * F;
        if constexpr (V == 2) {
            *(float2*)(yr + lane * 2)     = make_float2(acc0[0] * i0, acc0[1] * i0);
            *(float2*)(yr + F + lane * 2) = make_float2(acc1[0] * i1, acc1[1] * i1);
        } else {
            *(float4*)(yr + lane * 4) =
                make_float4(acc0[0] * i0, acc0[1] * i0, acc0[2] * i0, acc0[3] * i0);
            *(float4*)(yr + F + lane * 4) =
                make_float4(acc1[0] * i1, acc1[1] * i1, acc1[2] * i1, acc1[3] * i1);
        }
    }
}

// ---------------------- gemm1: f32x2 + BN stats + finalize ------------------
template <int TN>
__global__ __launch_bounds__(256) void gemm_kernel(
    const float* __restrict__ A, const float* __restrict__ B,
    const float* __restrict__ bias, const float* __restrict__ gamma,
    const float* __restrict__ beta, float* __restrict__ C,
    int M, int K, int ld)
{
    __shared__ float As[64 * 33];
    __shared__ float Bs[32 * TN];
    constexpr int CG = TN / 4;
    constexpr int RT = CG / 4;
    constexpr int TY = 256 / CG;
    const int tid = threadIdx.x;
    const int tx = tid % CG;
    const int ty = tid / CG;
    const int row0 = blockIdx.x * 64;
    const int cb = blockIdx.y * TN;
    unsigned long long acc[RT][2];
    #pragma unroll
    for (int i = 0; i < RT; i++) { acc[i][0] = 0ull; acc[i][1] = 0ull; }

    for (int k0 = 0; k0 < K; k0 += 32) {
        #pragma unroll
        for (int i = 0; i < 8; i++) {
            int idx = tid + i * 256;
            int r = idx >> 5, c = idx & 31;
            int gr = row0 + r;
            As[r * 33 + c] = (gr < M) ? A[(size_t)gr * ld + cb + k0 + c] : 0.f;
        }
        #pragma unroll
        for (int i = 0; i < TN / 8; i++) {
            int idx = tid + i * 256;
            int r = idx / TN, c = idx % TN;
            Bs[idx] = B[(size_t)(k0 + r) * ld + cb + c];
        }
        __syncthreads();
        #pragma unroll
        for (int kk = 0; kk < 32; kk++) {
            ulonglong2 bv = *(const ulonglong2*)&Bs[kk * TN + tx * 4];
            #pragma unroll
            for (int i = 0; i < RT; i++) {
                float a = As[(ty * RT + i) * 33 + kk];
                unsigned long long aa = pack2(a, a);
                ffma2(acc[i][0], aa, bv.x);
                ffma2(acc[i][1], aa, bv.y);
            }
        }
        __syncthreads();
    }
    float4 bv4 = *(const float4*)&bias[cb + tx * 4];
    float ls[4] = {0.f, 0.f, 0.f, 0.f};
    float lq[4] = {0.f, 0.f, 0.f, 0.f};
    #pragma unroll
    for (int i = 0; i < RT; i++) {
        int gr = row0 + ty * RT + i;
        if (gr < M) {
            float c0, c1, c2, c3;
            unpk2(acc[i][0], c0, c1);
            unpk2(acc[i][1], c2, c3);
            c0 += bv4.x; c1 += bv4.y; c2 += bv4.z; c3 += bv4.w;
            *(float4*)&C[(size_t)gr * ld + cb + tx * 4] =
                make_float4(c0, c1, c2, c3);
            ls[0] += c0; ls[1] += c1; ls[2] += c2; ls[3] += c3;
            lq[0] += c0 * c0; lq[1] += c1 * c1;
            lq[2] += c2 * c2; lq[3] += c3 * c3;
        }
    }
    #pragma unroll
    for (int j = 0; j < 4; j++) {
        As[ty * TN + tx * 4 + j] = ls[j];
        Bs[ty * TN + tx * 4 + j] = lq[j];
    }
    __syncthreads();
    if (tid < TN) {
        float s = 0.f, q = 0.f;
        #pragma unroll
        for (int yy = 0; yy < TY; yy++) {
            s += As[yy * TN + tid];
            q += Bs[yy * TN + tid];
        }
        int col = cb + tid;
        g_part[blockIdx.x * 2 * ld + col] = s;
        g_part[blockIdx.x * 2 * ld + ld + col] = q;
    }
    __shared__ int last;
    __threadfence();
    __syncthreads();
    if (tid == 0)
        last = (atomicAdd(&g_tick, 1) == (int)(gridDim.x * gridDim.y) - 1);
    __syncthreads();
    if (!last) return;
    for (int col = tid; col < ld; col += 256) {
        float s = 0.f, q = 0.f;
        for (int b = 0; b < GB; b++) {
            s += g_part[b * 2 * ld + col];
            q += g_part[b * 2 * ld + ld + col];
        }
        const float mu = s * (1.f / NN);
        const float var = q * (1.f / NN) - mu * mu;
        const float sc = gamma[col] * rsqrtf(var + 1e-5f);
        g_scale[col] = sc;
        g_shift[col] = beta[col] - mu * sc;
    }
    if (tid == 0) g_tick = 0;
}

// -------------- gemm2: split-fp16 tensor MMA + BN stats + finalize ----------
// A = y2 hi/lo [NN,256] fp16, B = W2^T hi/lo [256][128] fp16, C = out2 fp32.
// 8 warps (4m x 2n), warp tile 32x32, block tile 128x64; grid (157, 4).
__device__ __forceinline__ void mma16816(
    float* c, const unsigned* a, const unsigned* b)
{
    asm volatile(
        "mma.sync.aligned.m16n8k16.row.col.f32.f16.f16.f32 "
        "{%0,%1,%2,%3}, {%4,%5,%6,%7}, {%8,%9}, {%0,%1,%2,%3};"
        : "+f"(c[0]), "+f"(c[1]), "+f"(c[2]), "+f"(c[3])
        : "r"(a[0]), "r"(a[1]), "r"(a[2]), "r"(a[3]), "r"(b[0]), "r"(b[1]));
}

__global__ __launch_bounds__(256) void gemm2_mma_kernel(
    const __half* __restrict__ Ahi, const __half* __restrict__ Alo,
    const float* __restrict__ bias, const float* __restrict__ gamma,
    const float* __restrict__ beta, float* __restrict__ C)
{
    __shared__ float s_s[64], s_q[64];
    const int tid = threadIdx.x;
    const int warp = tid >> 5, lane = tid & 31;
    const int mw = warp & 3;
    const int nw = warp >> 2;
    const int head = blockIdx.y >> 1;
    const int nb = blockIdx.y & 1;
    const int row0 = blockIdx.x * 128 + mw * 32;
    const int cbA = head * 128;
    const int cbC = head * 128 + nb * 64;
    const int nbase = cbC + nw * 32;
    const int g = lane >> 2;
    const int tk = (lane & 3) * 2;
    if (tid < 64) { s_s[tid] = 0.f; s_q[tid] = 0.f; }

    float acc[2][4][4];
    #pragma unroll
    for (int mi = 0; mi < 2; mi++)
        #pragma unroll
        for (int ni = 0; ni < 4; ni++)
            #pragma unroll
            for (int j = 0; j < 4; j++) acc[mi][ni][j] = 0.f;

    #pragma unroll 1
    for (int k0 = 0; k0 < 128; k0 += 16) {
        unsigned ah[2][4], al[2][4];
        #pragma unroll
        for (int mi = 0; mi < 2; mi++) {
            int r0 = row0 + mi * 16 + g;
            int r1 = r0 + 8;
            bool o0 = r0 < NN, o1 = r1 < NN;
            size_t b0 = (size_t)r0 * 256 + cbA + k0 + tk;
            size_t b1 = (size_t)r1 * 256 + cbA + k0 + tk;
            ah[mi][0] = o0 ? *(const unsigned*)(Ahi + b0) : 0u;
            ah[mi][1] = o1 ? *(const unsigned*)(Ahi + b1) : 0u;
            ah[mi][2] = o0 ? *(const unsigned*)(Ahi + b0 + 8) : 0u;
            ah[mi][3] = o1 ? *(const unsigned*)(Ahi + b1 + 8) : 0u;
            al[mi][0] = o0 ? *(const unsigned*)(Alo + b0) : 0u;
            al[mi][1] = o1 ? *(const unsigned*)(Alo + b1) : 0u;
            al[mi][2] = o0 ? *(const unsigned*)(Alo + b0 + 8) : 0u;
            al[mi][3] = o1 ? *(const unsigned*)(Alo + b1 + 8) : 0u;
        }
        unsigned bh[4][2], bl[4][2];
        #pragma unroll
        for (int ni = 0; ni < 4; ni++) {
            size_t q = (size_t)(nbase + ni * 8 + g) * 128 + k0 + tk;
            bh[ni][0] = *(const unsigned*)(g_w2hi + q);
            bh[ni][1] = *(const unsigned*)(g_w2hi + q + 8);
            bl[ni][0] = *(const unsigned*)(g_w2lo + q);
            bl[ni][1] = *(const unsigned*)(g_w2lo + q + 8);
        }
        #pragma unroll
        for (int mi = 0; mi < 2; mi++)
            #pragma unroll
            for (int ni = 0; ni < 4; ni++) {
                mma16816(acc[mi][ni], ah[mi], bh[ni]);
                mma16816(acc[mi][ni], al[mi], bh[ni]);
                mma16816(acc[mi][ni], ah[mi], bl[ni]);
            }
    }
    __syncthreads();
    #pragma unroll
    for (int ni = 0; ni < 4; ni++) {
        const int col = nbase + ni * 8 + tk;
        float2 bv = *(const float2*)&bias[col];
        float s0 = 0.f, s1 = 0.f, q0 = 0.f, q1 = 0.f;
        #pragma unroll
        for (int mi = 0; mi < 2; mi++) {
            int r0 = row0 + mi * 16 + g;
            int r1 = r0 + 8;
            float c0 = acc[mi][ni][0] + bv.x;
            float c1 = acc[mi][ni][1] + bv.y;
            float c2 = acc[mi][ni][2] + bv.x;
            float c3 = acc[mi][ni][3] + bv.y;
            if (r0 < NN) {
                *(float2*)&C[(size_t)r0 * 256 + col] = make_float2(c0, c1);
                s0 += c0; s1 += c1; q0 += c0 * c0; q1 += c1 * c1;
            }
            if (r1 < NN) {
                *(float2*)&C[(size_t)r1 * 256 + col] = make_float2(c2, c3);
                s0 += c2; s1 += c3; q0 += c2 * c2; q1 += c3 * c3;
            }
        }
        #pragma unroll
        for (int o = 4; o < 32; o <<= 1) {
            s0 += __shfl_xor_sync(0xffffffffu, s0, o);
            s1 += __shfl_xor_sync(0xffffffffu, s1, o);
            q0 += __shfl_xor_sync(0xffffffffu, q0, o);
            q1 += __shfl_xor_sync(0xffffffffu, q1, o);
        }
        if (g == 0) {
            int cl = nw * 32 + ni * 8 + tk;
            atomicAdd(&s_s[cl], s0);     atomicAdd(&s_s[cl + 1], s1);
            atomicAdd(&s_q[cl], q0);     atomicAdd(&s_q[cl + 1], q1);
        }
    }
    __syncthreads();
    if (tid < 64) {
        g_part[blockIdx.x * 512 + cbC + tid] = s_s[tid];
        g_part[blockIdx.x * 512 + 256 + cbC + tid] = s_q[tid];
    }
    __shared__ int last;
    __threadfence();
    __syncthreads();
    if (tid == 0)
        last = (atomicAdd(&g_tick, 1) == (int)(gridDim.x * gridDim.y) - 1);
    __syncthreads();
    if (!last) return;
    {
        int col = tid;
        float s = 0.f, q = 0.f;
        for (int b = 0; b < GB2; b++) {
            s += g_part[b * 512 + col];
            q += g_part[b * 512 + 256 + col];
        }
        const float mu = s * (1.f / NN);
        const float var = q * (1.f / NN) - mu * mu;
        const float sc = gamma[col] * rsqrtf(var + 1e-5f);
        g_scale[col] = sc;
        g_shift[col] = beta[col] - mu * sc;
    }
    if (tid == 0) g_tick = 0;
}

__global__ void bnapply_kernel(const float* __restrict__ X,
                               float* __restrict__ Y, int mask, int total) {
    int i = blockIdx.x * blockDim.x + threadIdx.x;
    if (i >= total) return;
    int c = i & mask;
    float y = X[i] * g_scale[c] + g_shift[c];
    Y[i] = y > 0.f ? y : 0.f;
}

// ------------------------------- launcher -----------------------------------
extern "C" void kernel_launch(void* const* d_in, const int* in_sizes, int n_in,
                              void* d_out, int out_size) {
    const float* x        = (const float*)d_in[0];
    const void*  ei       = d_in[1];
    const float* W1       = (const float*)d_in[2];
    const float* att_src1 = (const float*)d_in[3];
    const float* att_dst1 = (const float*)d_in[4];
    const float* bias1    = (const float*)d_in[5];
    const float* gamma1   = (const float*)d_in[6];
    const float* beta1    = (const float*)d_in[7];
    const float* W2       = (const float*)d_in[8];
    const float* att_src2 = (const float*)d_in[9];
    const float* att_dst2 = (const float*)d_in[10];
    const float* bias2    = (const float*)d_in[11];
    const float* gamma2   = (const float*)d_in[12];
    const float* beta2    = (const float*)d_in[13];
    float* out = (float*)d_out;

    __half *x16, *h16, *y2hi, *y2lo;
    float *y1, *out1, *out2, *as1, *ad1, *as2, *ad2;
    float4 *u1, *u2;
    cudaGetSymbolAddress((void**)&x16,  g_x16);
    cudaGetSymbolAddress((void**)&h16,  g_h16);
    cudaGetSymbolAddress((void**)&y2hi, g_y2hi);
    cudaGetSymbolAddress((void**)&y2lo, g_y2lo);
    cudaGetSymbolAddress((void**)&y1,   g_y1);
    cudaGetSymbolAddress((void**)&out1, g_out1);
    cudaGetSymbolAddress((void**)&out2, g_out2);
    cudaGetSymbolAddress((void**)&as1,  g_as1);
    cudaGetSymbolAddress((void**)&ad1,  g_ad1);
    cudaGetSymbolAddress((void**)&as2,  g_as2);
    cudaGetSymbolAddress((void**)&ad2,  g_ad2);
    cudaGetSymbolAddress((void**)&u1,   g_u1);
    cudaGetSymbolAddress((void**)&u2,   g_u2);

    prep_kernel<<<135, 256>>>((const int*)ei, W1, att_src1, att_dst1,
                              W2, att_src2, att_dst2);
    hist_kernel<<<EE / 256, 256>>>(ei);
    rowptr_kernel<<<CB, 256>>>();
    scatter_gemv1_kernel<<<SB + NN / 8, 256>>>(ei, x, u1, as1, ad1, x16);

    agg_kernel<64, false><<<NN / 8, 256>>>(x16, as1, ad1, y1, nullptr, nullptr);
    gemm_kernel<64><<<dim3(GB, 2), 256>>>(y1, W1, bias1, gamma1, beta1,
                                          out1, NN, 64, 128);
    gemv2_kernel<<<NN / 8, 256>>>(out1, u2, as2, ad2, h16);
    agg_kernel<128, true><<<NN / 8, 256>>>(h16, as2, ad2, nullptr, y2hi, y2lo);
    gemm2_mma_kernel<<<dim3(GB2, 4), 256>>>(y2hi, y2lo, bias2, gamma2, beta2,
                                            out2);
    bnapply_kernel<<<(NN * 256 + 255) / 256, 256>>>(out2, out, 255, NN * 256);
}

// round 10
// speedup vs baseline: 1.2848x; 1.2848x over previous
#include <cuda_runtime.h>
#include <cuda_fp16.h>
#include <cuda_bf16.h>
#include <math.h>
#include <type_traits>

// ---------------------------------------------------------------------------
// GATLayers round 10 = R8 skeleton + gemm2 as smem-staged split-fp16 MMA.
//   A@B ~= Ahi@Bhi + Alo@Bhi + Ahi@Blo  (validated exact in R9: rel_err same)
// R9's failure was feeding (scattered global fragment LDGs); now the whole
// A/B tile is staged in 102KB dynamic smem via coalesced uint4 loads.
// ---------------------------------------------------------------------------

constexpr int NN = 20000;
constexpr int EE = 640000;
constexpr int CB = (NN + 255) / 256;   // 79 scan blocks
constexpr int GB = (NN + 63) / 64;     // 313 gemm1 row-blocks
constexpr int GB2 = (NN + 127) / 128;  // 157 gemm2 row-blocks
constexpr int PAD = 136;               // padded row stride (halves)
constexpr int SM2_BYTES = (2 * 128 * PAD + 2 * 64 * PAD) * 2;  // 104448

// ------------------------------ scratch ------------------------------------
__device__ int    g_is64;
__device__ int    g_ready;
__device__ int    g_done;
__device__ int    g_tick;
__device__ int    g_deg[NN];
__device__ int    g_rowptr[NN + 1];
__device__ int    g_rank[EE];
__device__ int    g_col[EE];
__device__ int    g_bsum[CB];
__device__ __half g_x16[NN * 64];
__device__ __half g_h16[NN * 128];
__device__ __half g_w2hi[256 * 128];   // W2^T hi fp16: [n][k]
__device__ __half g_w2lo[256 * 128];   // W2^T lo fp16
__device__ __half g_y2hi[NN * 256];    // aggregated layer2 hi
__device__ __half g_y2lo[NN * 256];    // aggregated layer2 lo
__device__ float  g_y1[NN * 128];
__device__ float  g_out1[NN * 128];
__device__ float  g_out2[NN * 256];
__device__ float  g_as1[NN * 2];
__device__ float  g_ad1[NN * 2];
__device__ float  g_as2[NN * 2];
__device__ float  g_ad2[NN * 2];
__device__ float  g_part[GB * 2 * 256];
__device__ float  g_scale[256];
__device__ float  g_shift[256];
__device__ float4 g_u1[64];
__device__ float4 g_u2[128];

// --------------------------- f32x2 helpers ----------------------------------
__device__ __forceinline__ unsigned long long pack2(float lo, float hi) {
    unsigned long long r;
    asm("mov.b64 %0, {%1, %2};" : "=l"(r)
        : "r"(__float_as_uint(lo)), "r"(__float_as_uint(hi)));
    return r;
}
__device__ __forceinline__ void unpk2(unsigned long long v, float& x, float& y) {
    unsigned a, b;
    asm("mov.b64 {%0, %1}, %2;" : "=r"(a), "=r"(b) : "l"(v));
    x = __uint_as_float(a); y = __uint_as_float(b);
}
__device__ __forceinline__ void ffma2(unsigned long long& d,
                                      unsigned long long a,
                                      unsigned long long b) {
    asm("fma.rn.f32x2 %0, %1, %2, %0;" : "+l"(d) : "l"(a), "l"(b));
}
__device__ __forceinline__ void split16(float v, __half& h, __half& l) {
    h = __float2half_rn(v);
    l = __float2half_rn(v - __half2float(h));
}

// ----------------- prep: deg zero + detect + attvec + W2 split --------------
__global__ __launch_bounds__(256) void prep_kernel(
    const int* __restrict__ ei32,
    const float* __restrict__ W1, const float* __restrict__ s1,
    const float* __restrict__ d1,
    const float* __restrict__ W2, const float* __restrict__ s2,
    const float* __restrict__ d2)
{
    const int bx = blockIdx.x;
    if (bx < 79) {
        int i = bx * 256 + threadIdx.x;
        if (i < NN) g_deg[i] = 0;
        if (bx == 0 && threadIdx.x < 32) {
            int lane = threadIdx.x;
            int a = ei32[2 * lane + 1];
            int b = ei32[2 * (lane + 32) + 1];
            unsigned m = __ballot_sync(0xffffffffu, (a | b) != 0);
            if (lane == 0) g_is64 = (m == 0) ? 1 : 0;
        }
        return;
    }
    if (bx < 103) {
        const int lane = threadIdx.x & 31;
        const int f = (bx - 79) * 8 + (threadIdx.x >> 5);   // 0..191
        float4 u = make_float4(0.f, 0.f, 0.f, 0.f);
        if (f < 64) {
            #pragma unroll
            for (int c = lane; c < 64; c += 32) {
                float w0 = W1[f * 128 + c], w1 = W1[f * 128 + 64 + c];
                u.x += w0 * s1[c];      u.y += w1 * s1[64 + c];
                u.z += w0 * d1[c];      u.w += w1 * d1[64 + c];
            }
        } else {
            int f2 = f - 64;
            #pragma unroll
            for (int c = lane; c < 128; c += 32) {
                float w0 = W2[f2 * 256 + c], w1 = W2[f2 * 256 + 128 + c];
                u.x += w0 * s2[c];      u.y += w1 * s2[128 + c];
                u.z += w0 * d2[c];      u.w += w1 * d2[128 + c];
            }
        }
        #pragma unroll
        for (int o = 16; o; o >>= 1) {
            u.x += __shfl_xor_sync(0xffffffffu, u.x, o);
            u.y += __shfl_xor_sync(0xffffffffu, u.y, o);
            u.z += __shfl_xor_sync(0xffffffffu, u.z, o);
            u.w += __shfl_xor_sync(0xffffffffu, u.w, o);
        }
        if (lane == 0) {
            if (f < 64) g_u1[f] = u;
            else        g_u2[f - 64] = u;
        }
        return;
    }
    // W2^T split-fp16: blocks 103..134
    int t4 = (bx - 103) * 256 + threadIdx.x;       // 0..8191
    int e = t4 * 4;
    int k = e >> 8;
    int n0 = e & 255;
    float4 w = *(const float4*)&W2[k * 256 + n0];
    __half h, l;
    split16(w.x, h, l); g_w2hi[(n0 + 0) * 128 + k] = h; g_w2lo[(n0 + 0) * 128 + k] = l;
    split16(w.y, h, l); g_w2hi[(n0 + 1) * 128 + k] = h; g_w2lo[(n0 + 1) * 128 + k] = l;
    split16(w.z, h, l); g_w2hi[(n0 + 2) * 128 + k] = h; g_w2lo[(n0 + 2) * 128 + k] = l;
    split16(w.w, h, l); g_w2hi[(n0 + 3) * 128 + k] = h; g_w2lo[(n0 + 3) * 128 + k] = l;
}

// -------------------------- CSR construction -------------------------------
__device__ __forceinline__ int edge_val(const void* ei, int idx, int is64) {
    if (is64) return (int)((const long long*)ei)[idx];
    return ((const int*)ei)[idx];
}

__global__ void hist_kernel(const void* __restrict__ ei) {
    int e = blockIdx.x * blockDim.x + threadIdx.x;
    if (e >= EE) return;
    int dst = edge_val(ei, EE + e, g_is64);
    g_rank[e] = atomicAdd(&g_deg[dst], 1);
}

__global__ __launch_bounds__(256) void rowptr_kernel() {
    __shared__ int s[256];
    const int t = threadIdx.x;
    const int bx = blockIdx.x;
    const int i = bx * 256 + t;
    int d = (i < NN) ? g_deg[i] : 0;
    s[t] = d;
    __syncthreads();
    for (int o = 1; o < 256; o <<= 1) {
        int u = (t >= o) ? s[t - o] : 0;
        __syncthreads();
        s[t] += u;
        __syncthreads();
    }
    const int incl = s[t];
    if (t == 255) {
        g_bsum[bx] = incl;
        __threadfence();
        atomicAdd(&g_ready, 1);
        while (atomicAdd(&g_ready, 0) < (int)gridDim.x) {}
    }
    __syncthreads();
    int pre = 0;
    for (int b = t; b < bx; b += 256) pre += g_bsum[b];
    #pragma unroll
    for (int o = 16; o; o >>= 1) pre += __shfl_xor_sync(0xffffffffu, pre, o);
    __shared__ int ws[8];
    if ((t & 31) == 0) ws[t >> 5] = pre;
    __syncthreads();
    if (t == 0) {
        int p = 0;
        #pragma unroll
        for (int w = 0; w < 8; w++) p += ws[w];
        s[0] = p;
    }
    __syncthreads();
    const int bpre = s[0];
    if (i < NN) g_rowptr[i] = bpre + incl - d;
    if (i == NN - 1) g_rowptr[NN] = bpre + incl;
    if (t == 0 && atomicAdd(&g_done, 1) == (int)gridDim.x - 1) {
        g_ready = 0;
        g_done = 0;
    }
}

// ---------------- fused scatter (blocks < SB) + gemv1 (rest) ----------------
constexpr int SB = EE / 256;

template <int K, bool BN>
__device__ __forceinline__ void gemv_body(
    int node, const float* __restrict__ A, const float4* __restrict__ U,
    float* __restrict__ as_out, float* __restrict__ ad_out,
    __half* __restrict__ h16, int lane)
{
    float4 acc = make_float4(0.f, 0.f, 0.f, 0.f);
    #pragma unroll
    for (int f = lane; f < K; f += 32) {
        float v = A[(size_t)node * K + f];
        if (BN) { v = v * g_scale[f] + g_shift[f]; v = v > 0.f ? v : 0.f; }
        h16[(size_t)node * K + f] = __float2half_rn(v);
        float4 u = U[f];
        acc.x += v * u.x; acc.y += v * u.y;
        acc.z += v * u.z; acc.w += v * u.w;
    }
    #pragma unroll
    for (int o = 16; o; o >>= 1) {
        acc.x += __shfl_xor_sync(0xffffffffu, acc.x, o);
        acc.y += __shfl_xor_sync(0xffffffffu, acc.y, o);
        acc.z += __shfl_xor_sync(0xffffffffu, acc.z, o);
        acc.w += __shfl_xor_sync(0xffffffffu, acc.w, o);
    }
    if (lane == 0) {
        as_out[node * 2 + 0] = acc.x;
        as_out[node * 2 + 1] = acc.y;
        ad_out[node * 2 + 0] = acc.z;
        ad_out[node * 2 + 1] = acc.w;
    }
}

__global__ __launch_bounds__(256) void scatter_gemv1_kernel(
    const void* __restrict__ ei, const float* __restrict__ x,
    const float4* __restrict__ U,
    float* __restrict__ as_out, float* __restrict__ ad_out,
    __half* __restrict__ x16)
{
    const int bx = blockIdx.x;
    if (bx < SB) {
        int e = bx * 256 + threadIdx.x;
        int is64 = g_is64;
        int src = edge_val(ei, e, is64);
        int dst = edge_val(ei, EE + e, is64);
        g_col[g_rowptr[dst] + g_rank[e]] = src;
        return;
    }
    const int node = (bx - SB) * 8 + (threadIdx.x >> 5);
    gemv_body<64, false>(node, x, U, as_out, ad_out, x16, threadIdx.x & 31);
}

__global__ __launch_bounds__(256) void gemv2_kernel(
    const float* __restrict__ A, const float4* __restrict__ U,
    float* __restrict__ as_out, float* __restrict__ ad_out,
    __half* __restrict__ h16)
{
    const int node = blockIdx.x * 8 + (threadIdx.x >> 5);
    gemv_body<128, true>(node, A, U, as_out, ad_out, h16, threadIdx.x & 31);
}

// ------------------- segment softmax + weighted aggregate ------------------
template <int F, bool SPLIT>
__global__ __launch_bounds__(256) void agg_kernel(
    const __half* __restrict__ src16, const float* __restrict__ as,
    const float* __restrict__ ad, float* __restrict__ y,
    __half* __restrict__ yhi, __half* __restrict__ ylo)
{
    const int lane = threadIdx.x & 31;
    const int warp = threadIdx.x >> 5;
    const int node = blockIdx.x * 8 + warp;
    constexpr int V = F / 32;
    using RowT = typename std::conditional<V == 2, unsigned, uint2>::type;
    const int base = g_rowptr[node];
    const int deg = g_rowptr[node + 1] - base;
    const float2* as2 = (const float2*)as;
    const float2 adi = ((const float2*)ad)[node];

    float acc0[V], acc1[V];
    #pragma unroll
    for (int v = 0; v < V; v++) { acc0[v] = 0.f; acc1[v] = 0.f; }
    float zp0 = 0.f, zp1 = 0.f;

    auto accum = [&](RowT u, float p0, float p1) {
        if constexpr (V == 2) {
            float2 f = __half22float2(*(__half2*)&u);
            acc0[0] += p0 * f.x; acc0[1] += p0 * f.y;
            acc1[0] += p1 * f.x; acc1[1] += p1 * f.y;
        } else {
            float2 f0 = __half22float2(*(__half2*)&u.x);
            float2 f1 = __half22float2(*(__half2*)&u.y);
            acc0[0] += p0 * f0.x; acc0[1] += p0 * f0.y;
            acc0[2] += p0 * f1.x; acc0[3] += p0 * f1.y;
            acc1[0] += p1 * f0.x; acc1[1] += p1 * f0.y;
            acc1[2] += p1 * f1.x; acc1[3] += p1 * f1.y;
        }
    };

    {   // self loop
        float2 a = as2[node];
        float e0 = a.x + adi.x; e0 = e0 > 0.f ? e0 : 0.2f * e0;
        float e1 = a.y + adi.y; e1 = e1 > 0.f ? e1 : 0.2f * e1;
        float p0 = __expf(e0), p1 = __expf(e1);
        if (lane == 0) { zp0 += p0; zp1 += p1; }
        RowT u = *(const RowT*)(src16 + (size_t)node * F + lane * V);
        accum(u, p0, p1);
    }

    for (int j0 = 0; j0 < deg; j0 += 32) {
        const int nb = min(32, deg - j0);
        int sl = 0; float p0 = 0.f, p1 = 0.f;
        if (lane < nb) {
            sl = g_col[base + j0 + lane];
            float2 a = as2[sl];
            float e0 = a.x + adi.x; e0 = e0 > 0.f ? e0 : 0.2f * e0;
            float e1 = a.y + adi.y; e1 = e1 > 0.f ? e1 : 0.2f * e1;
            p0 = __expf(e0); p1 = __expf(e1);
        }
        zp0 += p0; zp1 += p1;
        if (nb == 32) {
            #pragma unroll 8
            for (int k = 0; k < 32; k++) {
                int sk = __shfl_sync(0xffffffffu, sl, k);
                float q0 = __shfl_sync(0xffffffffu, p0, k);
                float q1 = __shfl_sync(0xffffffffu, p1, k);
                RowT u = *(const RowT*)(src16 + (size_t)sk * F + lane * V);
                accum(u, q0, q1);
            }
        } else {
            for (int k = 0; k < nb; k++) {
                int sk = __shfl_sync(0xffffffffu, sl, k);
                float q0 = __shfl_sync(0xffffffffu, p0, k);
                float q1 = __shfl_sync(0xffffffffu, p1, k);
                RowT u = *(const RowT*)(src16 + (size_t)sk * F + lane * V);
                accum(u, q0, q1);
            }
        }
    }

    #pragma unroll
    for (int o = 16; o; o >>= 1) {
        zp0 += __shfl_xor_sync(0xffffffffu, zp0, o);
        zp1 += __shfl_xor_sync(0xffffffffu, zp1, o);
    }
    const float i0 = 1.f / zp0, i1 = 1.f / zp1;

    if constexpr (SPLIT) {
        float v0[4], v1[4];
        #pragma unroll
        for (int v = 0; v < 4; v++) { v0[v] = acc0[v] * i0; v1[v] = acc1[v] * i1; }
        __half h[8], l[8];
        #pragma unroll
        for (int v = 0; v < 4; v++) split16(v0[v], h[v], l[v]);
        #pragma unroll
        for (int v = 0; v < 4; v++) split16(v1[v], h[4 + v], l[4 + v]);
        size_t off0 = (size_t)node * 2 * F + lane * 4;
        size_t off1 = off0 + F;
        *(uint2*)(yhi + off0) = *(uint2*)&h[0];
        *(uint2*)(yhi + off1) = *(uint2*)&h[4];
        *(uint2*)(ylo + off0) = *(uint2*)&l[0];
        *(uint2*)(ylo + off1) = *(uint2*)&l[4];
    } else {
        float* yr = y + (size_t)node * 2 * F;
        if constexpr (V == 2) {
            *(float2*)(yr + lane * 2)     = make_float2(acc0[0] * i0, acc0[1] * i0);
            *(float2*)(yr + F + lane * 2) = make_float2(acc1[0] * i1, acc1[1] * i1);
        } else {
            *(float4*)(yr + lane * 4) =
                make_float4(acc0[0] * i0, acc0[1] * i0, acc0[2] * i0, acc0[3] * i0);
            *(float4*)(yr + F + lane * 4) =
                make_float4(acc1[0] * i1, acc1[1] * i1, acc1[2] * i1, acc1[3] * i1);
        }
    }
}

// ---------------------- gemm1: f32x2 + BN stats + finalize ------------------
template <int TN>
__global__ __launch_bounds__(256) void gemm_kernel(
    const float* __restrict__ A, const float* __restrict__ B,
    const float* __restrict__ bias, const float* __restrict__ gamma,
    const float* __restrict__ beta, float* __restrict__ C,
    int M, int K, int ld)
{
    __shared__ float As[64 * 33];
    __shared__ float Bs[32 * TN];
    constexpr int CG = TN / 4;
    constexpr int RT = CG / 4;
    constexpr int TY = 256 / CG;
    const int tid = threadIdx.x;
    const int tx = tid % CG;
    const int ty = tid / CG;
    const int row0 = blockIdx.x * 64;
    const int cb = blockIdx.y * TN;
    unsigned long long acc[RT][2];
    #pragma unroll
    for (int i = 0; i < RT; i++) { acc[i][0] = 0ull; acc[i][1] = 0ull; }

    for (int k0 = 0; k0 < K; k0 += 32) {
        #pragma unroll
        for (int i = 0; i < 8; i++) {
            int idx = tid + i * 256;
            int r = idx >> 5, c = idx & 31;
            int gr = row0 + r;
            As[r * 33 + c] = (gr < M) ? A[(size_t)gr * ld + cb + k0 + c] : 0.f;
        }
        #pragma unroll
        for (int i = 0; i < TN / 8; i++) {
            int idx = tid + i * 256;
            int r = idx / TN, c = idx % TN;
            Bs[idx] = B[(size_t)(k0 + r) * ld + cb + c];
        }
        __syncthreads();
        #pragma unroll
        for (int kk = 0; kk < 32; kk++) {
            ulonglong2 bv = *(const ulonglong2*)&Bs[kk * TN + tx * 4];
            #pragma unroll
            for (int i = 0; i < RT; i++) {
                float a = As[(ty * RT + i) * 33 + kk];
                unsigned long long aa = pack2(a, a);
                ffma2(acc[i][0], aa, bv.x);
                ffma2(acc[i][1], aa, bv.y);
            }
        }
        __syncthreads();
    }
    float4 bv4 = *(const float4*)&bias[cb + tx * 4];
    float ls[4] = {0.f, 0.f, 0.f, 0.f};
    float lq[4] = {0.f, 0.f, 0.f, 0.f};
    #pragma unroll
    for (int i = 0; i < RT; i++) {
        int gr = row0 + ty * RT + i;
        if (gr < M) {
            float c0, c1, c2, c3;
            unpk2(acc[i][0], c0, c1);
            unpk2(acc[i][1], c2, c3);
            c0 += bv4.x; c1 += bv4.y; c2 += bv4.z; c3 += bv4.w;
            *(float4*)&C[(size_t)gr * ld + cb + tx * 4] =
                make_float4(c0, c1, c2, c3);
            ls[0] += c0; ls[1] += c1; ls[2] += c2; ls[3] += c3;
            lq[0] += c0 * c0; lq[1] += c1 * c1;
            lq[2] += c2 * c2; lq[3] += c3 * c3;
        }
    }
    #pragma unroll
    for (int j = 0; j < 4; j++) {
        As[ty * TN + tx * 4 + j] = ls[j];
        Bs[ty * TN + tx * 4 + j] = lq[j];
    }
    __syncthreads();
    if (tid < TN) {
        float s = 0.f, q = 0.f;
        #pragma unroll
        for (int yy = 0; yy < TY; yy++) {
            s += As[yy * TN + tid];
            q += Bs[yy * TN + tid];
        }
        int col = cb + tid;
        g_part[blockIdx.x * 2 * ld + col] = s;
        g_part[blockIdx.x * 2 * ld + ld + col] = q;
    }
    __shared__ int last;
    __threadfence();
    __syncthreads();
    if (tid == 0)
        last = (atomicAdd(&g_tick, 1) == (int)(gridDim.x * gridDim.y) - 1);
    __syncthreads();
    if (!last) return;
    for (int col = tid; col < ld; col += 256) {
        float s = 0.f, q = 0.f;
        for (int b = 0; b < GB; b++) {
            s += g_part[b * 2 * ld + col];
            q += g_part[b * 2 * ld + ld + col];
        }
        const float mu = s * (1.f / NN);
        const float var = q * (1.f / NN) - mu * mu;
        const float sc = gamma[col] * rsqrtf(var + 1e-5f);
        g_scale[col] = sc;
        g_shift[col] = beta[col] - mu * sc;
    }
    if (tid == 0) g_tick = 0;
}

// -------- gemm2: smem-staged split-fp16 tensor MMA + BN stats ---------------
__device__ __forceinline__ void mma16816(
    float* c, const unsigned* a, const unsigned* b)
{
    asm volatile(
        "mma.sync.aligned.m16n8k16.row.col.f32.f16.f16.f32 "
        "{%0,%1,%2,%3}, {%4,%5,%6,%7}, {%8,%9}, {%0,%1,%2,%3};"
        : "+f"(c[0]), "+f"(c[1]), "+f"(c[2]), "+f"(c[3])
        : "r"(a[0]), "r"(a[1]), "r"(a[2]), "r"(a[3]), "r"(b[0]), "r"(b[1]));
}

__global__ __launch_bounds__(256) void gemm2_mma_kernel(
    const __half* __restrict__ Ahi, const __half* __restrict__ Alo,
    const float* __restrict__ bias, const float* __restrict__ gamma,
    const float* __restrict__ beta, float* __restrict__ C)
{
    extern __shared__ __half sm[];
    __half* sAhi = sm;
    __half* sAlo = sm + 128 * PAD;
    __half* sBhi = sm + 2 * 128 * PAD;
    __half* sBlo = sBhi + 64 * PAD;
    __shared__ float s_s[64], s_q[64];

    const int tid = threadIdx.x;
    const int warp = tid >> 5, lane = tid & 31;
    const int mw = warp & 3;
    const int nw = warp >> 2;
    const int head = blockIdx.y >> 1;
    const int nb = blockIdx.y & 1;
    const int row0b = blockIdx.x * 128;
    const int cbA = head * 128;
    const int cbC = head * 128 + nb * 64;
    const int g = lane >> 2;
    const int tk = (lane & 3) * 2;
    if (tid < 64) { s_s[tid] = 0.f; s_q[tid] = 0.f; }

    // ---- stage A tile (128 rows x 128 k, hi+lo) coalesced ----
    #pragma unroll
    for (int i = tid; i < 2048; i += 256) {      // 16 uint4 per row
        int r = i >> 4;
        int c8 = (i & 15) * 8;
        int gr = row0b + r;
        uint4 vh = make_uint4(0u, 0u, 0u, 0u);
        uint4 vl = vh;
        if (gr < NN) {
            vh = *(const uint4*)(Ahi + (size_t)gr * 256 + cbA + c8);
            vl = *(const uint4*)(Alo + (size_t)gr * 256 + cbA + c8);
        }
        *(uint4*)(sAhi + r * PAD + c8) = vh;
        *(uint4*)(sAlo + r * PAD + c8) = vl;
    }
    // ---- stage B tile (64 n x 128 k, hi+lo) ----
    #pragma unroll
    for (int i = tid; i < 1024; i += 256) {
        int n = i >> 4;
        int c8 = (i & 15) * 8;
        uint4 vh = *(const uint4*)(g_w2hi + (size_t)(cbC + n) * 128 + c8);
        uint4 vl = *(const uint4*)(g_w2lo + (size_t)(cbC + n) * 128 + c8);
        *(uint4*)(sBhi + n * PAD + c8) = vh;
        *(uint4*)(sBlo + n * PAD + c8) = vl;
    }
    __syncthreads();

    float acc[2][4][4];
    #pragma unroll
    for (int mi = 0; mi < 2; mi++)
        #pragma unroll
        for (int ni = 0; ni < 4; ni++)
            #pragma unroll
            for (int j = 0; j < 4; j++) acc[mi][ni][j] = 0.f;

    #pragma unroll 1
    for (int k0 = 0; k0 < 128; k0 += 16) {
        unsigned ah[2][4], al[2][4];
        #pragma unroll
        for (int mi = 0; mi < 2; mi++) {
            int row = mw * 32 + mi * 16 + g;
            const __half* p = sAhi + row * PAD + k0 + tk;
            const __half* q = sAlo + row * PAD + k0 + tk;
            ah[mi][0] = *(const unsigned*)p;
            ah[mi][1] = *(const unsigned*)(p + 8 * PAD);
            ah[mi][2] = *(const unsigned*)(p + 8);
            ah[mi][3] = *(const unsigned*)(p + 8 * PAD + 8);
            al[mi][0] = *(const unsigned*)q;
            al[mi][1] = *(const unsigned*)(q + 8 * PAD);
            al[mi][2] = *(const unsigned*)(q + 8);
            al[mi][3] = *(const unsigned*)(q + 8 * PAD + 8);
        }
        unsigned bh[4][2], bl[4][2];
        #pragma unroll
        for (int ni = 0; ni < 4; ni++) {
            int n = nw * 32 + ni * 8 + g;
            const __half* p = sBhi + n * PAD + k0 + tk;
            const __half* q = sBlo + n * PAD + k0 + tk;
            bh[ni][0] = *(const unsigned*)p;
            bh[ni][1] = *(const unsigned*)(p + 8);
            bl[ni][0] = *(const unsigned*)q;
            bl[ni][1] = *(const unsigned*)(q + 8);
        }
        #pragma unroll
        for (int mi = 0; mi < 2; mi++)
            #pragma unroll
            for (int ni = 0; ni < 4; ni++) {
                mma16816(acc[mi][ni], ah[mi], bh[ni]);
                mma16816(acc[mi][ni], al[mi], bh[ni]);
                mma16816(acc[mi][ni], ah[mi], bl[ni]);
            }
    }
    __syncthreads();
    // ---- epilogue: bias, store, column partial sums (validated in R9) ----
    const int nbase = cbC + nw * 32;
    #pragma unroll
    for (int ni = 0; ni < 4; ni++) {
        const int col = nbase + ni * 8 + tk;
        float2 bv = *(const float2*)&bias[col];
        float s0 = 0.f, s1 = 0.f, q0 = 0.f, q1 = 0.f;
        #pragma unroll
        for (int mi = 0; mi < 2; mi++) {
            int r0 = row0b + mw * 32 + mi * 16 + g;
            int r1 = r0 + 8;
            float c0 = acc[mi][ni][0] + bv.x;
            float c1 = acc[mi][ni][1] + bv.y;
            float c2 = acc[mi][ni][2] + bv.x;
            float c3 = acc[mi][ni][3] + bv.y;
            if (r0 < NN) {
                *(float2*)&C[(size_t)r0 * 256 + col] = make_float2(c0, c1);
                s0 += c0; s1 += c1; q0 += c0 * c0; q1 += c1 * c1;
            }
            if (r1 < NN) {
                *(float2*)&C[(size_t)r1 * 256 + col] = make_float2(c2, c3);
                s0 += c2; s1 += c3; q0 += c2 * c2; q1 += c3 * c3;
            }
        }
        #pragma unroll
        for (int o = 4; o < 32; o <<= 1) {
            s0 += __shfl_xor_sync(0xffffffffu, s0, o);
            s1 += __shfl_xor_sync(0xffffffffu, s1, o);
            q0 += __shfl_xor_sync(0xffffffffu, q0, o);
            q1 += __shfl_xor_sync(0xffffffffu, q1, o);
        }
        if (g == 0) {
            int cl = nw * 32 + ni * 8 + tk;
            atomicAdd(&s_s[cl], s0);     atomicAdd(&s_s[cl + 1], s1);
            atomicAdd(&s_q[cl], q0);     atomicAdd(&s_q[cl + 1], q1);
        }
    }
    __syncthreads();
    if (tid < 64) {
        g_part[blockIdx.x * 512 + cbC + tid] = s_s[tid];
        g_part[blockIdx.x * 512 + 256 + cbC + tid] = s_q[tid];
    }
    __shared__ int last;
    __threadfence();
    __syncthreads();
    if (tid == 0)
        last = (atomicAdd(&g_tick, 1) == (int)(gridDim.x * gridDim.y) - 1);
    __syncthreads();
    if (!last) return;
    {
        int col = tid;
        float s = 0.f, q = 0.f;
        for (int b = 0; b < GB2; b++) {
            s += g_part[b * 512 + col];
            q += g_part[b * 512 + 256 + col];
        }
        const float mu = s * (1.f / NN);
        const float var = q * (1.f / NN) - mu * mu;
        const float sc = gamma[col] * rsqrtf(var + 1e-5f);
        g_scale[col] = sc;
        g_shift[col] = beta[col] - mu * sc;
    }
    if (tid == 0) g_tick = 0;
}

__global__ void bnapply_kernel(const float4* __restrict__ X,
                               float4* __restrict__ Y, int total4) {
    int i = blockIdx.x * blockDim.x + threadIdx.x;
    if (i >= total4) return;
    int c = (i & 63) * 4;             // 256 cols = 64 float4 per row
    float4 v = X[i];
    float4 sc = *(const float4*)&g_scale[c];
    float4 sh = *(const float4*)&g_shift[c];
    v.x = fmaxf(v.x * sc.x + sh.x, 0.f);
    v.y = fmaxf(v.y * sc.y + sh.y, 0.f);
    v.z = fmaxf(v.z * sc.z + sh.z, 0.f);
    v.w = fmaxf(v.w * sc.w + sh.w, 0.f);
    Y[i] = v;
}

// ------------------------------- launcher -----------------------------------
extern "C" void kernel_launch(void* const* d_in, const int* in_sizes, int n_in,
                              void* d_out, int out_size) {
    const float* x        = (const float*)d_in[0];
    const void*  ei       = d_in[1];
    const float* W1       = (const float*)d_in[2];
    const float* att_src1 = (const float*)d_in[3];
    const float* att_dst1 = (const float*)d_in[4];
    const float* bias1    = (const float*)d_in[5];
    const float* gamma1   = (const float*)d_in[6];
    const float* beta1    = (const float*)d_in[7];
    const float* W2       = (const float*)d_in[8];
    const float* att_src2 = (const float*)d_in[9];
    const float* att_dst2 = (const float*)d_in[10];
    const float* bias2    = (const float*)d_in[11];
    const float* gamma2   = (const float*)d_in[12];
    const float* beta2    = (const float*)d_in[13];
    float* out = (float*)d_out;

    __half *x16, *h16, *y2hi, *y2lo;
    float *y1, *out1, *out2, *as1, *ad1, *as2, *ad2;
    float4 *u1, *u2;
    cudaGetSymbolAddress((void**)&x16,  g_x16);
    cudaGetSymbolAddress((void**)&h16,  g_h16);
    cudaGetSymbolAddress((void**)&y2hi, g_y2hi);
    cudaGetSymbolAddress((void**)&y2lo, g_y2lo);
    cudaGetSymbolAddress((void**)&y1,   g_y1);
    cudaGetSymbolAddress((void**)&out1, g_out1);
    cudaGetSymbolAddress((void**)&out2, g_out2);
    cudaGetSymbolAddress((void**)&as1,  g_as1);
    cudaGetSymbolAddress((void**)&ad1,  g_ad1);
    cudaGetSymbolAddress((void**)&as2,  g_as2);
    cudaGetSymbolAddress((void**)&ad2,  g_ad2);
    cudaGetSymbolAddress((void**)&u1,   g_u1);
    cudaGetSymbolAddress((void**)&u2,   g_u2);

    cudaFuncSetAttribute(gemm2_mma_kernel,
                         cudaFuncAttributeMaxDynamicSharedMemorySize,
                         SM2_BYTES);

    prep_kernel<<<135, 256>>>((const int*)ei, W1, att_src1, att_dst1,
                              W2, att_src2, att_dst2);
    hist_kernel<<<EE / 256, 256>>>(ei);
    rowptr_kernel<<<CB, 256>>>();
    scatter_gemv1_kernel<<<SB + NN / 8, 256>>>(ei, x, u1, as1, ad1, x16);

    agg_kernel<64, false><<<NN / 8, 256>>>(x16, as1, ad1, y1, nullptr, nullptr);
    gemm_kernel<64><<<dim3(GB, 2), 256>>>(y1, W1, bias1, gamma1, beta1,
                                          out1, NN, 64, 128);
    gemv2_kernel<<<NN / 8, 256>>>(out1, u2, as2, ad2, h16);
    agg_kernel<128, true><<<NN / 8, 256>>>(h16, as2, ad2, nullptr, y2hi, y2lo);
    gemm2_mma_kernel<<<dim3(GB2, 4), 256, SM2_BYTES>>>(y2hi, y2lo, bias2,
                                                       gamma2, beta2, out2);
    bnapply_kernel<<<(NN * 64 + 255) / 256, 256>>>((const float4*)out2,
                                                   (float4*)out, NN * 64);
}

// round 11
// speedup vs baseline: 1.3251x; 1.0314x over previous
#include <cuda_runtime.h>
#include <cuda_fp16.h>
#include <cuda_bf16.h>
#include <math.h>
#include <type_traits>

// ---------------------------------------------------------------------------
// GATLayers round 11 = R10 + gemm1 on the same smem-staged split-fp16 MMA
// + hist merged into prep (per-block is64 ballot) + deg reset inside rowptr.
// 9 graph nodes:
//  prep(hist+attvec+Wsplit) | rowptr | scatter+gemv1 | agg1(split) |
//  gemm1_mma(+BN) | gemv2 | agg2(split) | gemm2_mma(+BN) | bnapply
// ---------------------------------------------------------------------------

constexpr int NN = 20000;
constexpr int EE = 640000;
constexpr int CB = (NN + 255) / 256;   // 79 scan blocks
constexpr int HB = EE / 256;           // 2500 hist/scatter blocks
constexpr int GB2 = (NN + 127) / 128;  // 157 mma row-blocks
constexpr int PAD2 = 136;              // gemm2 smem row stride (halves)
constexpr int PAD1 = 72;               // gemm1 smem row stride (halves)
constexpr int SM2_BYTES = (2 * 128 * PAD2 + 2 * 64 * PAD2) * 2;  // 104448
constexpr int SM1_BYTES = (2 * 128 * PAD1 + 2 * 64 * PAD1) * 2;  // 55296

// ------------------------------ scratch ------------------------------------
__device__ int    g_is64;
__device__ int    g_ready;
__device__ int    g_done;
__device__ int    g_tick;
__device__ int    g_deg[NN];
__device__ int    g_rowptr[NN + 1];
__device__ int    g_rank[EE];
__device__ int    g_col[EE];
__device__ int    g_bsum[CB];
__device__ __half g_x16[NN * 64];
__device__ __half g_h16[NN * 128];
__device__ __half g_w1hi[128 * 64];    // W1^T hi fp16: [n][k]
__device__ __half g_w1lo[128 * 64];
__device__ __half g_w2hi[256 * 128];   // W2^T hi fp16: [n][k]
__device__ __half g_w2lo[256 * 128];
__device__ __half g_y1hi[NN * 128];    // aggregated layer1 hi
__device__ __half g_y1lo[NN * 128];
__device__ __half g_y2hi[NN * 256];    // aggregated layer2 hi
__device__ __half g_y2lo[NN * 256];
__device__ float  g_out1[NN * 128];
__device__ float  g_out2[NN * 256];
__device__ float  g_as1[NN * 2];
__device__ float  g_ad1[NN * 2];
__device__ float  g_as2[NN * 2];
__device__ float  g_ad2[NN * 2];
__device__ float  g_part[GB2 * 2 * 256];
__device__ float  g_scale[256];
__device__ float  g_shift[256];
__device__ float4 g_u1[64];
__device__ float4 g_u2[128];

// ------------------------------ helpers -------------------------------------
__device__ __forceinline__ void split16(float v, __half& h, __half& l) {
    h = __float2half_rn(v);
    l = __float2half_rn(v - __half2float(h));
}
__device__ __forceinline__ int edge_val(const void* ei, int idx, int is64) {
    if (is64) return (int)((const long long*)ei)[idx];
    return ((const int*)ei)[idx];
}
__device__ __forceinline__ void mma16816(
    float* c, const unsigned* a, const unsigned* b)
{
    asm volatile(
        "mma.sync.aligned.m16n8k16.row.col.f32.f16.f16.f32 "
        "{%0,%1,%2,%3}, {%4,%5,%6,%7}, {%8,%9}, {%0,%1,%2,%3};"
        : "+f"(c[0]), "+f"(c[1]), "+f"(c[2]), "+f"(c[3])
        : "r"(a[0]), "r"(a[1]), "r"(a[2]), "r"(a[3]), "r"(b[0]), "r"(b[1]));
}

// -------- prep: hist (per-block is64) + attvec + W2/W1 split-fp16 -----------
// blocks [0,2500): hist; [2500,2524): attvec; [2524,2556): W2T; [2556,2564): W1T
__global__ __launch_bounds__(256) void prep_kernel(
    const void* __restrict__ ei,
    const float* __restrict__ W1, const float* __restrict__ s1,
    const float* __restrict__ d1,
    const float* __restrict__ W2, const float* __restrict__ s2,
    const float* __restrict__ d2)
{
    const int bx = blockIdx.x;
    const int tid = threadIdx.x;
    if (bx < HB) {
        const int* ei32 = (const int*)ei;
        __shared__ int s_is64;
        if (tid < 32) {
            int a = ei32[2 * tid + 1];
            int b = ei32[2 * (tid + 32) + 1];
            unsigned m = __ballot_sync(0xffffffffu, (a | b) != 0);
            if (tid == 0) {
                s_is64 = (m == 0) ? 1 : 0;
                if (bx == 0) g_is64 = s_is64;
            }
        }
        __syncthreads();
        const int is64 = s_is64;
        int e = bx * 256 + tid;
        int dst = edge_val(ei, EE + e, is64);
        g_rank[e] = atomicAdd(&g_deg[dst], 1);
        return;
    }
    if (bx < HB + 24) {    // attention vectors
        const int lane = tid & 31;
        const int f = (bx - HB) * 8 + (tid >> 5);   // 0..191
        float4 u = make_float4(0.f, 0.f, 0.f, 0.f);
        if (f < 64) {
            #pragma unroll
            for (int c = lane; c < 64; c += 32) {
                float w0 = W1[f * 128 + c], w1 = W1[f * 128 + 64 + c];
                u.x += w0 * s1[c];      u.y += w1 * s1[64 + c];
                u.z += w0 * d1[c];      u.w += w1 * d1[64 + c];
            }
        } else {
            int f2 = f - 64;
            #pragma unroll
            for (int c = lane; c < 128; c += 32) {
                float w0 = W2[f2 * 256 + c], w1 = W2[f2 * 256 + 128 + c];
                u.x += w0 * s2[c];      u.y += w1 * s2[128 + c];
                u.z += w0 * d2[c];      u.w += w1 * d2[128 + c];
            }
        }
        #pragma unroll
        for (int o = 16; o; o >>= 1) {
            u.x += __shfl_xor_sync(0xffffffffu, u.x, o);
            u.y += __shfl_xor_sync(0xffffffffu, u.y, o);
            u.z += __shfl_xor_sync(0xffffffffu, u.z, o);
            u.w += __shfl_xor_sync(0xffffffffu, u.w, o);
        }
        if (lane == 0) {
            if (f < 64) g_u1[f] = u;
            else        g_u2[f - 64] = u;
        }
        return;
    }
    if (bx < HB + 56) {   // W2^T split: 32 blocks, 32768 elems
        int t4 = (bx - HB - 24) * 256 + tid;
        int e = t4 * 4;
        int k = e >> 8;
        int n0 = e & 255;
        float4 w = *(const float4*)&W2[k * 256 + n0];
        __half h, l;
        split16(w.x, h, l); g_w2hi[(n0 + 0) * 128 + k] = h; g_w2lo[(n0 + 0) * 128 + k] = l;
        split16(w.y, h, l); g_w2hi[(n0 + 1) * 128 + k] = h; g_w2lo[(n0 + 1) * 128 + k] = l;
        split16(w.z, h, l); g_w2hi[(n0 + 2) * 128 + k] = h; g_w2lo[(n0 + 2) * 128 + k] = l;
        split16(w.w, h, l); g_w2hi[(n0 + 3) * 128 + k] = h; g_w2lo[(n0 + 3) * 128 + k] = l;
        return;
    }
    {   // W1^T split: 8 blocks, 8192 elems
        int t4 = (bx - HB - 56) * 256 + tid;
        int e = t4 * 4;
        int k = e >> 7;             // 0..63
        int n0 = e & 127;
        float4 w = *(const float4*)&W1[k * 128 + n0];
        __half h, l;
        split16(w.x, h, l); g_w1hi[(n0 + 0) * 64 + k] = h; g_w1lo[(n0 + 0) * 64 + k] = l;
        split16(w.y, h, l); g_w1hi[(n0 + 1) * 64 + k] = h; g_w1lo[(n0 + 1) * 64 + k] = l;
        split16(w.z, h, l); g_w1hi[(n0 + 2) * 64 + k] = h; g_w1lo[(n0 + 2) * 64 + k] = l;
        split16(w.w, h, l); g_w1hi[(n0 + 3) * 64 + k] = h; g_w1lo[(n0 + 3) * 64 + k] = l;
    }
}

// ----------------- rowptr: scan + spin + deg reset for next replay ----------
__global__ __launch_bounds__(256) void rowptr_kernel() {
    __shared__ int s[256];
    const int t = threadIdx.x;
    const int bx = blockIdx.x;
    const int i = bx * 256 + t;
    int d = (i < NN) ? g_deg[i] : 0;
    if (i < NN) g_deg[i] = 0;          // reset for next graph replay
    s[t] = d;
    __syncthreads();
    for (int o = 1; o < 256; o <<= 1) {
        int u = (t >= o) ? s[t - o] : 0;
        __syncthreads();
        s[t] += u;
        __syncthreads();
    }
    const int incl = s[t];
    if (t == 255) {
        g_bsum[bx] = incl;
        __threadfence();
        atomicAdd(&g_ready, 1);
        while (atomicAdd(&g_ready, 0) < (int)gridDim.x) {}
    }
    __syncthreads();
    int pre = 0;
    for (int b = t; b < bx; b += 256) pre += g_bsum[b];
    #pragma unroll
    for (int o = 16; o; o >>= 1) pre += __shfl_xor_sync(0xffffffffu, pre, o);
    __shared__ int ws[8];
    if ((t & 31) == 0) ws[t >> 5] = pre;
    __syncthreads();
    if (t == 0) {
        int p = 0;
        #pragma unroll
        for (int w = 0; w < 8; w++) p += ws[w];
        s[0] = p;
    }
    __syncthreads();
    const int bpre = s[0];
    if (i < NN) g_rowptr[i] = bpre + incl - d;
    if (i == NN - 1) g_rowptr[NN] = bpre + incl;
    if (t == 0 && atomicAdd(&g_done, 1) == (int)gridDim.x - 1) {
        g_ready = 0;
        g_done = 0;
    }
}

// ---------------- fused scatter (blocks < HB) + gemv1 (rest) ----------------
template <int K, bool BN>
__device__ __forceinline__ void gemv_body(
    int node, const float* __restrict__ A, const float4* __restrict__ U,
    float* __restrict__ as_out, float* __restrict__ ad_out,
    __half* __restrict__ h16, int lane)
{
    float4 acc = make_float4(0.f, 0.f, 0.f, 0.f);
    #pragma unroll
    for (int f = lane; f < K; f += 32) {
        float v = A[(size_t)node * K + f];
        if (BN) { v = v * g_scale[f] + g_shift[f]; v = v > 0.f ? v : 0.f; }
        h16[(size_t)node * K + f] = __float2half_rn(v);
        float4 u = U[f];
        acc.x += v * u.x; acc.y += v * u.y;
        acc.z += v * u.z; acc.w += v * u.w;
    }
    #pragma unroll
    for (int o = 16; o; o >>= 1) {
        acc.x += __shfl_xor_sync(0xffffffffu, acc.x, o);
        acc.y += __shfl_xor_sync(0xffffffffu, acc.y, o);
        acc.z += __shfl_xor_sync(0xffffffffu, acc.z, o);
        acc.w += __shfl_xor_sync(0xffffffffu, acc.w, o);
    }
    if (lane == 0) {
        as_out[node * 2 + 0] = acc.x;
        as_out[node * 2 + 1] = acc.y;
        ad_out[node * 2 + 0] = acc.z;
        ad_out[node * 2 + 1] = acc.w;
    }
}

__global__ __launch_bounds__(256) void scatter_gemv1_kernel(
    const void* __restrict__ ei, const float* __restrict__ x,
    const float4* __restrict__ U,
    float* __restrict__ as_out, float* __restrict__ ad_out,
    __half* __restrict__ x16)
{
    const int bx = blockIdx.x;
    if (bx < HB) {
        int e = bx * 256 + threadIdx.x;
        int is64 = g_is64;
        int src = edge_val(ei, e, is64);
        int dst = edge_val(ei, EE + e, is64);
        g_col[g_rowptr[dst] + g_rank[e]] = src;
        return;
    }
    const int node = (bx - HB) * 8 + (threadIdx.x >> 5);
    gemv_body<64, false>(node, x, U, as_out, ad_out, x16, threadIdx.x & 31);
}

__global__ __launch_bounds__(256) void gemv2_kernel(
    const float* __restrict__ A, const float4* __restrict__ U,
    float* __restrict__ as_out, float* __restrict__ ad_out,
    __half* __restrict__ h16)
{
    const int node = blockIdx.x * 8 + (threadIdx.x >> 5);
    gemv_body<128, true>(node, A, U, as_out, ad_out, h16, threadIdx.x & 31);
}

// ------------------- segment softmax + weighted aggregate ------------------
// Batched-32 edges per warp; emits split hi/lo fp16 y (both layers).
template <int F>
__global__ __launch_bounds__(256) void agg_kernel(
    const __half* __restrict__ src16, const float* __restrict__ as,
    const float* __restrict__ ad,
    __half* __restrict__ yhi, __half* __restrict__ ylo)
{
    const int lane = threadIdx.x & 31;
    const int warp = threadIdx.x >> 5;
    const int node = blockIdx.x * 8 + warp;
    constexpr int V = F / 32;
    using RowT = typename std::conditional<V == 2, unsigned, uint2>::type;
    const int base = g_rowptr[node];
    const int deg = g_rowptr[node + 1] - base;
    const float2* as2 = (const float2*)as;
    const float2 adi = ((const float2*)ad)[node];

    float acc0[V], acc1[V];
    #pragma unroll
    for (int v = 0; v < V; v++) { acc0[v] = 0.f; acc1[v] = 0.f; }
    float zp0 = 0.f, zp1 = 0.f;

    auto accum = [&](RowT u, float p0, float p1) {
        if constexpr (V == 2) {
            float2 f = __half22float2(*(__half2*)&u);
            acc0[0] += p0 * f.x; acc0[1] += p0 * f.y;
            acc1[0] += p1 * f.x; acc1[1] += p1 * f.y;
        } else {
            float2 f0 = __half22float2(*(__half2*)&u.x);
            float2 f1 = __half22float2(*(__half2*)&u.y);
            acc0[0] += p0 * f0.x; acc0[1] += p0 * f0.y;
            acc0[2] += p0 * f1.x; acc0[3] += p0 * f1.y;
            acc1[0] += p1 * f0.x; acc1[1] += p1 * f0.y;
            acc1[2] += p1 * f1.x; acc1[3] += p1 * f1.y;
        }
    };

    {   // self loop
        float2 a = as2[node];
        float e0 = a.x + adi.x; e0 = e0 > 0.f ? e0 : 0.2f * e0;
        float e1 = a.y + adi.y; e1 = e1 > 0.f ? e1 : 0.2f * e1;
        float p0 = __expf(e0), p1 = __expf(e1);
        if (lane == 0) { zp0 += p0; zp1 += p1; }
        RowT u = *(const RowT*)(src16 + (size_t)node * F + lane * V);
        accum(u, p0, p1);
    }

    for (int j0 = 0; j0 < deg; j0 += 32) {
        const int nb = min(32, deg - j0);
        int sl = 0; float p0 = 0.f, p1 = 0.f;
        if (lane < nb) {
            sl = g_col[base + j0 + lane];
            float2 a = as2[sl];
            float e0 = a.x + adi.x; e0 = e0 > 0.f ? e0 : 0.2f * e0;
            float e1 = a.y + adi.y; e1 = e1 > 0.f ? e1 : 0.2f * e1;
            p0 = __expf(e0); p1 = __expf(e1);
        }
        zp0 += p0; zp1 += p1;
        if (nb == 32) {
            #pragma unroll 8
            for (int k = 0; k < 32; k++) {
                int sk = __shfl_sync(0xffffffffu, sl, k);
                float q0 = __shfl_sync(0xffffffffu, p0, k);
                float q1 = __shfl_sync(0xffffffffu, p1, k);
                RowT u = *(const RowT*)(src16 + (size_t)sk * F + lane * V);
                accum(u, q0, q1);
            }
        } else {
            for (int k = 0; k < nb; k++) {
                int sk = __shfl_sync(0xffffffffu, sl, k);
                float q0 = __shfl_sync(0xffffffffu, p0, k);
                float q1 = __shfl_sync(0xffffffffu, p1, k);
                RowT u = *(const RowT*)(src16 + (size_t)sk * F + lane * V);
                accum(u, q0, q1);
            }
        }
    }

    #pragma unroll
    for (int o = 16; o; o >>= 1) {
        zp0 += __shfl_xor_sync(0xffffffffu, zp0, o);
        zp1 += __shfl_xor_sync(0xffffffffu, zp1, o);
    }
    const float i0 = 1.f / zp0, i1 = 1.f / zp1;

    if constexpr (V == 2) {
        __half h0, l0, h1, l1, h2, l2, h3, l3;
        split16(acc0[0] * i0, h0, l0);
        split16(acc0[1] * i0, h1, l1);
        split16(acc1[0] * i1, h2, l2);
        split16(acc1[1] * i1, h3, l3);
        size_t off0 = (size_t)node * 2 * F + lane * 2;
        size_t off1 = off0 + F;
        __half2 vh0 = __halves2half2(h0, h1), vl0 = __halves2half2(l0, l1);
        __half2 vh1 = __halves2half2(h2, h3), vl1 = __halves2half2(l2, l3);
        *(__half2*)(yhi + off0) = vh0;
        *(__half2*)(yhi + off1) = vh1;
        *(__half2*)(ylo + off0) = vl0;
        *(__half2*)(ylo + off1) = vl1;
    } else {
        float v0[4], v1[4];
        #pragma unroll
        for (int v = 0; v < 4; v++) { v0[v] = acc0[v] * i0; v1[v] = acc1[v] * i1; }
        __half h[8], l[8];
        #pragma unroll
        for (int v = 0; v < 4; v++) split16(v0[v], h[v], l[v]);
        #pragma unroll
        for (int v = 0; v < 4; v++) split16(v1[v], h[4 + v], l[4 + v]);
        size_t off0 = (size_t)node * 2 * F + lane * 4;
        size_t off1 = off0 + F;
        *(uint2*)(yhi + off0) = *(uint2*)&h[0];
        *(uint2*)(yhi + off1) = *(uint2*)&h[4];
        *(uint2*)(ylo + off0) = *(uint2*)&l[0];
        *(uint2*)(ylo + off1) = *(uint2*)&l[4];
    }
}

// ------- shared MMA gemm: smem-staged split-fp16, + BN stats + finalize -----
// Template over K (64 or 128) and output width per head (=64 N per block).
// grid (157, NY): blockIdx.y encodes head (and n-block for layer2).
template <int K, int LD, int NY, int PAD>
__global__ __launch_bounds__(256) void gemm_mma_kernel(
    const __half* __restrict__ Ahi, const __half* __restrict__ Alo,
    const __half* __restrict__ Whi, const __half* __restrict__ Wlo,
    const float* __restrict__ bias, const float* __restrict__ gamma,
    const float* __restrict__ beta, float* __restrict__ C)
{
    extern __shared__ __half sm[];
    __half* sAhi = sm;
    __half* sAlo = sm + 128 * PAD;
    __half* sBhi = sm + 2 * 128 * PAD;
    __half* sBlo = sBhi + 64 * PAD;
    __shared__ float s_s[64], s_q[64];

    const int tid = threadIdx.x;
    const int warp = tid >> 5, lane = tid & 31;
    const int mw = warp & 3;
    const int nw = warp >> 2;
    // head / n-block decode: LD==128 -> NY=2 (by=head); LD==256 -> NY=4
    const int head = (NY == 2) ? (int)blockIdx.y : ((int)blockIdx.y >> 1);
    const int nb = (NY == 2) ? 0 : ((int)blockIdx.y & 1);
    const int row0b = blockIdx.x * 128;
    const int cbA = head * K;            // A cols per head = K
    const int cbC = head * (LD / 2) + nb * 64;
    const int g = lane >> 2;
    const int tk = (lane & 3) * 2;
    if (tid < 64) { s_s[tid] = 0.f; s_q[tid] = 0.f; }

    // ---- stage A tile (128 rows x K, hi+lo) ----
    constexpr int AU = 128 * K / 8;      // uint4 count per buffer
    #pragma unroll
    for (int i = tid; i < AU; i += 256) {
        int r = i / (K / 8);
        int c8 = (i % (K / 8)) * 8;
        int gr = row0b + r;
        uint4 vh = make_uint4(0u, 0u, 0u, 0u);
        uint4 vl = vh;
        if (gr < NN) {
            vh = *(const uint4*)(Ahi + (size_t)gr * LD + cbA + c8);
            vl = *(const uint4*)(Alo + (size_t)gr * LD + cbA + c8);
        }
        *(uint4*)(sAhi + r * PAD + c8) = vh;
        *(uint4*)(sAlo + r * PAD + c8) = vl;
    }
    // ---- stage B tile (64 n x K, hi+lo) ----
    constexpr int BU = 64 * K / 8;
    #pragma unroll
    for (int i = tid; i < BU; i += 256) {
        int n = i / (K / 8);
        int c8 = (i % (K / 8)) * 8;
        uint4 vh = *(const uint4*)(Whi + (size_t)(cbC + n) * K + c8);
        uint4 vl = *(const uint4*)(Wlo + (size_t)(cbC + n) * K + c8);
        *(uint4*)(sBhi + n * PAD + c8) = vh;
        *(uint4*)(sBlo + n * PAD + c8) = vl;
    }
    __syncthreads();

    float acc[2][4][4];
    #pragma unroll
    for (int mi = 0; mi < 2; mi++)
        #pragma unroll
        for (int ni = 0; ni < 4; ni++)
            #pragma unroll
            for (int j = 0; j < 4; j++) acc[mi][ni][j] = 0.f;

    #pragma unroll 1
    for (int k0 = 0; k0 < K; k0 += 16) {
        unsigned ah[2][4], al[2][4];
        #pragma unroll
        for (int mi = 0; mi < 2; mi++) {
            int row = mw * 32 + mi * 16 + g;
            const __half* p = sAhi + row * PAD + k0 + tk;
            const __half* q = sAlo + row * PAD + k0 + tk;
            ah[mi][0] = *(const unsigned*)p;
            ah[mi][1] = *(const unsigned*)(p + 8 * PAD);
            ah[mi][2] = *(const unsigned*)(p + 8);
            ah[mi][3] = *(const unsigned*)(p + 8 * PAD + 8);
            al[mi][0] = *(const unsigned*)q;
            al[mi][1] = *(const unsigned*)(q + 8 * PAD);
            al[mi][2] = *(const unsigned*)(q + 8);
            al[mi][3] = *(const unsigned*)(q + 8 * PAD + 8);
        }
        unsigned bh[4][2], bl[4][2];
        #pragma unroll
        for (int ni = 0; ni < 4; ni++) {
            int n = nw * 32 + ni * 8 + g;
            const __half* p = sBhi + n * PAD + k0 + tk;
            const __half* q = sBlo + n * PAD + k0 + tk;
            bh[ni][0] = *(const unsigned*)p;
            bh[ni][1] = *(const unsigned*)(p + 8);
            bl[ni][0] = *(const unsigned*)q;
            bl[ni][1] = *(const unsigned*)(q + 8);
        }
        #pragma unroll
        for (int mi = 0; mi < 2; mi++)
            #pragma unroll
            for (int ni = 0; ni < 4; ni++) {
                mma16816(acc[mi][ni], ah[mi], bh[ni]);
                mma16816(acc[mi][ni], al[mi], bh[ni]);
                mma16816(acc[mi][ni], ah[mi], bl[ni]);
            }
    }
    __syncthreads();
    // ---- epilogue: bias, store, BN column partials ----
    const int nbase = cbC + nw * 32;
    #pragma unroll
    for (int ni = 0; ni < 4; ni++) {
        const int col = nbase + ni * 8 + tk;
        float2 bv = *(const float2*)&bias[col];
        float s0 = 0.f, s1 = 0.f, q0 = 0.f, q1 = 0.f;
        #pragma unroll
        for (int mi = 0; mi < 2; mi++) {
            int r0 = row0b + mw * 32 + mi * 16 + g;
            int r1 = r0 + 8;
            float c0 = acc[mi][ni][0] + bv.x;
            float c1 = acc[mi][ni][1] + bv.y;
            float c2 = acc[mi][ni][2] + bv.x;
            float c3 = acc[mi][ni][3] + bv.y;
            if (r0 < NN) {
                *(float2*)&C[(size_t)r0 * LD + col] = make_float2(c0, c1);
                s0 += c0; s1 += c1; q0 += c0 * c0; q1 += c1 * c1;
            }
            if (r1 < NN) {
                *(float2*)&C[(size_t)r1 * LD + col] = make_float2(c2, c3);
                s0 += c2; s1 += c3; q0 += c2 * c2; q1 += c3 * c3;
            }
        }
        #pragma unroll
        for (int o = 4; o < 32; o <<= 1) {
            s0 += __shfl_xor_sync(0xffffffffu, s0, o);
            s1 += __shfl_xor_sync(0xffffffffu, s1, o);
            q0 += __shfl_xor_sync(0xffffffffu, q0, o);
            q1 += __shfl_xor_sync(0xffffffffu, q1, o);
        }
        if (g == 0) {
            int cl = nw * 32 + ni * 8 + tk;
            atomicAdd(&s_s[cl], s0);     atomicAdd(&s_s[cl + 1], s1);
            atomicAdd(&s_q[cl], q0);     atomicAdd(&s_q[cl + 1], q1);
        }
    }
    __syncthreads();
    if (tid < 64) {
        g_part[blockIdx.x * 2 * LD + cbC + tid] = s_s[tid];
        g_part[blockIdx.x * 2 * LD + LD + cbC + tid] = s_q[tid];
    }
    __shared__ int last;
    __threadfence();
    __syncthreads();
    if (tid == 0)
        last = (atomicAdd(&g_tick, 1) == (int)(gridDim.x * gridDim.y) - 1);
    __syncthreads();
    if (!last) return;
    for (int col = tid; col < LD; col += 256) {
        float s = 0.f, q = 0.f;
        for (int b = 0; b < GB2; b++) {
            s += g_part[b * 2 * LD + col];
            q += g_part[b * 2 * LD + LD + col];
        }
        const float mu = s * (1.f / NN);
        const float var = q * (1.f / NN) - mu * mu;
        const float sc = gamma[col] * rsqrtf(var + 1e-5f);
        g_scale[col] = sc;
        g_shift[col] = beta[col] - mu * sc;
    }
    if (tid == 0) g_tick = 0;
}

__global__ void bnapply_kernel(const float4* __restrict__ X,
                               float4* __restrict__ Y, int total4) {
    int i = blockIdx.x * blockDim.x + threadIdx.x;
    if (i >= total4) return;
    int c = (i & 63) * 4;
    float4 v = X[i];
    float4 sc = *(const float4*)&g_scale[c];
    float4 sh = *(const float4*)&g_shift[c];
    v.x = fmaxf(v.x * sc.x + sh.x, 0.f);
    v.y = fmaxf(v.y * sc.y + sh.y, 0.f);
    v.z = fmaxf(v.z * sc.z + sh.z, 0.f);
    v.w = fmaxf(v.w * sc.w + sh.w, 0.f);
    Y[i] = v;
}

// ------------------------------- launcher -----------------------------------
extern "C" void kernel_launch(void* const* d_in, const int* in_sizes, int n_in,
                              void* d_out, int out_size) {
    const float* x        = (const float*)d_in[0];
    const void*  ei       = d_in[1];
    const float* W1       = (const float*)d_in[2];
    const float* att_src1 = (const float*)d_in[3];
    const float* att_dst1 = (const float*)d_in[4];
    const float* bias1    = (const float*)d_in[5];
    const float* gamma1   = (const float*)d_in[6];
    const float* beta1    = (const float*)d_in[7];
    const float* W2       = (const float*)d_in[8];
    const float* att_src2 = (const float*)d_in[9];
    const float* att_dst2 = (const float*)d_in[10];
    const float* bias2    = (const float*)d_in[11];
    const float* gamma2   = (const float*)d_in[12];
    const float* beta2    = (const float*)d_in[13];
    float* out = (float*)d_out;

    __half *x16, *h16, *y1hi, *y1lo, *y2hi, *y2lo, *w1hi, *w1lo, *w2hi, *w2lo;
    float *out1, *out2, *as1, *ad1, *as2, *ad2;
    float4 *u1, *u2;
    cudaGetSymbolAddress((void**)&x16,  g_x16);
    cudaGetSymbolAddress((void**)&h16,  g_h16);
    cudaGetSymbolAddress((void**)&y1hi, g_y1hi);
    cudaGetSymbolAddress((void**)&y1lo, g_y1lo);
    cudaGetSymbolAddress((void**)&y2hi, g_y2hi);
    cudaGetSymbolAddress((void**)&y2lo, g_y2lo);
    cudaGetSymbolAddress((void**)&w1hi, g_w1hi);
    cudaGetSymbolAddress((void**)&w1lo, g_w1lo);
    cudaGetSymbolAddress((void**)&w2hi, g_w2hi);
    cudaGetSymbolAddress((void**)&w2lo, g_w2lo);
    cudaGetSymbolAddress((void**)&out1, g_out1);
    cudaGetSymbolAddress((void**)&out2, g_out2);
    cudaGetSymbolAddress((void**)&as1,  g_as1);
    cudaGetSymbolAddress((void**)&ad1,  g_ad1);
    cudaGetSymbolAddress((void**)&as2,  g_as2);
    cudaGetSymbolAddress((void**)&ad2,  g_ad2);
    cudaGetSymbolAddress((void**)&u1,   g_u1);
    cudaGetSymbolAddress((void**)&u2,   g_u2);

    cudaFuncSetAttribute((const void*)gemm_mma_kernel<64, 128, 2, PAD1>,
                         cudaFuncAttributeMaxDynamicSharedMemorySize,
                         SM1_BYTES);
    cudaFuncSetAttribute((const void*)gemm_mma_kernel<128, 256, 4, PAD2>,
                         cudaFuncAttributeMaxDynamicSharedMemorySize,
                         SM2_BYTES);

    prep_kernel<<<HB + 64, 256>>>(ei, W1, att_src1, att_dst1,
                                  W2, att_src2, att_dst2);
    rowptr_kernel<<<CB, 256>>>();
    scatter_gemv1_kernel<<<HB + NN / 8, 256>>>(ei, x, u1, as1, ad1, x16);

    agg_kernel<64><<<NN / 8, 256>>>(x16, as1, ad1, y1hi, y1lo);
    gemm_mma_kernel<64, 128, 2, PAD1><<<dim3(GB2, 2), 256, SM1_BYTES>>>(
        y1hi, y1lo, w1hi, w1lo, bias1, gamma1, beta1, out1);
    gemv2_kernel<<<NN / 8, 256>>>(out1, u2, as2, ad2, h16);
    agg_kernel<128><<<NN / 8, 256>>>(h16, as2, ad2, y2hi, y2lo);
    gemm_mma_kernel<128, 256, 4, PAD2><<<dim3(GB2, 4), 256, SM2_BYTES>>>(
        y2hi, y2lo, w2hi, w2lo, bias2, gamma2, beta2, out2);
    bnapply_kernel<<<(NN * 64 + 255) / 256, 256>>>((const float4*)out2,
                                                   (float4*)out, NN * 64);
}